// round 10
// baseline (speedup 1.0000x reference)
#include <cuda_runtime.h>
#include <math.h>
#include <stdint.h>

#define T_STEPS 512
#define BATCH   64
#define IN_DIM  256
#define HID     512
#define OUT_DIM 256
#define BH      (BATCH * HID)        // 32768
#define M_ROWS  (T_STEPS * BATCH)    // 32768

// Scratch (allocation-free rule: __device__ globals)
__device__ float g_xp[(size_t)M_ROWS * HID];   // xp = x@W_ih^T + b_ih + b_hh
__device__ float g_rnn[(size_t)M_ROWS * HID];  // rnn_out (h history)

// fast tanh: rel err ~1e-6, clamped (no NaN)
__device__ __forceinline__ float tanh_fast(float x) {
    float xc = fminf(9.0f, fmaxf(-9.0f, x));
    float e  = exp2f(2.885390081777927f * xc);   // e^(2x)
    return __fdividef(e - 1.0f, e + 1.0f);
}

// -------------------- SGEMM: C[M,N] = A[M,K] @ Bw[N,K]^T + bias --------------------
template<int BM, int BN, int BK, int TM, int TN, int THREADS>
__global__ __launch_bounds__(THREADS)
void sgemm_bt_bias(const float* __restrict__ A,
                   const float* __restrict__ Bw,
                   const float* __restrict__ bias0,
                   const float* __restrict__ bias1,
                   float* __restrict__ C,
                   int M, int N, int K)
{
    __shared__ float As[BK][BM];
    __shared__ float Bs[BK][BN];

    const int tid = threadIdx.x;
    const int tx  = tid % (BN / TN);
    const int ty  = tid / (BN / TN);
    const int m0  = blockIdx.y * BM;
    const int n0  = blockIdx.x * BN;

    float acc[TM][TN];
    #pragma unroll
    for (int i = 0; i < TM; ++i)
        #pragma unroll
        for (int j = 0; j < TN; ++j) acc[i][j] = 0.f;

    for (int k0 = 0; k0 < K; k0 += BK) {
        #pragma unroll
        for (int i = tid; i < (BM * BK) / 4; i += THREADS) {
            int r  = i / (BK / 4);
            int c4 = i % (BK / 4);
            float4 v = *(const float4*)&A[(size_t)(m0 + r) * K + k0 + c4 * 4];
            As[c4 * 4 + 0][r] = v.x;
            As[c4 * 4 + 1][r] = v.y;
            As[c4 * 4 + 2][r] = v.z;
            As[c4 * 4 + 3][r] = v.w;
        }
        #pragma unroll
        for (int i = tid; i < (BN * BK) / 4; i += THREADS) {
            int r  = i / (BK / 4);
            int c4 = i % (BK / 4);
            float4 v = *(const float4*)&Bw[(size_t)(n0 + r) * K + k0 + c4 * 4];
            Bs[c4 * 4 + 0][r] = v.x;
            Bs[c4 * 4 + 1][r] = v.y;
            Bs[c4 * 4 + 2][r] = v.z;
            Bs[c4 * 4 + 3][r] = v.w;
        }
        __syncthreads();

        #pragma unroll
        for (int kk = 0; kk < BK; ++kk) {
            float aR[TM], bR[TN];
            #pragma unroll
            for (int i = 0; i < TM; ++i) aR[i] = As[kk][ty * TM + i];
            #pragma unroll
            for (int j = 0; j < TN; ++j) bR[j] = Bs[kk][tx * TN + j];
            #pragma unroll
            for (int i = 0; i < TM; ++i)
                #pragma unroll
                for (int j = 0; j < TN; ++j)
                    acc[i][j] += aR[i] * bR[j];
        }
        __syncthreads();
    }

    float bj[TN];
    #pragma unroll
    for (int j = 0; j < TN; ++j) {
        int n = n0 + tx * TN + j;
        bj[j] = bias0[n] + (bias1 ? bias1[n] : 0.f);
    }
    #pragma unroll
    for (int i = 0; i < TM; ++i) {
        int m = m0 + ty * TM + i;
        #pragma unroll
        for (int j = 0; j < TN; ++j) {
            int n = n0 + tx * TN + j;
            C[(size_t)m * N + n] = acc[i][j] + bj[j];
        }
    }
}

// -------------------- recurrent scan v7: register-tiled + clusters ------------------
// 128 CTAs = 16 clusters (4 batches each) x 8 CTAs (64 cols each).
// Thread = (c-pair, b-pair, ks of 4 k-splits): 2x2 output tile, K/4 = 128 MACs range.
// 4 B/MAC LDS traffic (vs 8 before); shfl reduction over ks; DSMEM h exchange.
#define CLUSTER_N 8
#define NCLUSTERS 16
#define COLS_CTA  64
#define BPG       4
#define WSTR      516                      // sW row stride (floats)
#define HROW      528                      // sH batch-row stride: 4 chunks x 132
#define SW_FLOATS (COLS_CTA * WSTR)        // 33024
#define SH_FLOATS (2 * BPG * HROW)         // 4224 (ping-pong)
#define SC_FLOATS (BPG * COLS_CTA)         // 256
#define SMEM_SCAN_BYTES ((SW_FLOATS + SH_FLOATS + SC_FLOATS) * 4)   // 150016

// h float4-index m (0..127) -> float offset within a batch row (chunk-padded)
#define H_OFF(m) (((m) >> 5) * 132 + ((m) & 31) * 4)

__device__ __forceinline__ uint32_t smem_u32(const void* p) {
    uint32_t a;
    asm("{ .reg .u64 t; cvta.to.shared.u64 t, %1; cvt.u32.u64 %0, t; }"
        : "=r"(a) : "l"(p));
    return a;
}
__device__ __forceinline__ uint32_t mapa32(uint32_t addr, int rank) {
    uint32_t r;
    asm("mapa.shared::cluster.u32 %0, %1, %2;" : "=r"(r) : "r"(addr), "r"(rank));
    return r;
}
__device__ __forceinline__ void st_cluster_v4(uint32_t addr, float4 v) {
    asm volatile("st.shared::cluster.v4.f32 [%0], {%1,%2,%3,%4};"
                 :: "r"(addr), "f"(v.x), "f"(v.y), "f"(v.z), "f"(v.w) : "memory");
}
__device__ __forceinline__ void st_shared_v4(uint32_t addr, float4 v) {
    asm volatile("st.shared.v4.f32 [%0], {%1,%2,%3,%4};"
                 :: "r"(addr), "f"(v.x), "f"(v.y), "f"(v.z), "f"(v.w) : "memory");
}
__device__ __forceinline__ void cluster_sync_() {
    asm volatile("barrier.cluster.arrive.aligned;" ::: "memory");
    asm volatile("barrier.cluster.wait.aligned;" ::: "memory");
}
#define FMA2(acc, a, b) asm("fma.rn.f32x2 %0, %1, %2, %0;" : "+l"(acc) : "l"(a), "l"(b))

__global__ __launch_bounds__(256, 1) __cluster_dims__(CLUSTER_N, 1, 1)
void rnn_scan7(const float* __restrict__ Whh,   // [HID, HID]
               float* __restrict__ h_out)       // [BATCH, HID]
{
    extern __shared__ float sm[];
    float* sW = sm;                     // [64][WSTR]
    float* sH = sm + SW_FLOATS;         // [2][BPG][HROW]
    float* sC = sH + SH_FLOATS;         // [BPG][64]

    const int tid  = threadIdx.x;
    const int g    = blockIdx.x >> 3;   // batch group 0..15
    const int rank = blockIdx.x & 7;    // col group within cluster

    const int ks   = tid & 3;           // k-split 0..3
    const int tile = tid >> 2;          // 0..63
    const int c2   = tile & 31;         // col-pair index
    const int b2   = tile >> 5;         // batch-pair index (0..1)
    const int c0   = 2 * c2;            // local col base (0..62)
    const int b0l  = 2 * b2;            // local batch base (0 or 2)
    const int cG   = rank * COLS_CTA + c0;
    const int bG   = g * BPG + b0l;

    // load W_hh rows [rank*64, +64) into SMEM
    for (int i = tid; i < COLS_CTA * (HID / 4); i += 256) {
        int r  = i >> 7;
        int k4 = i & 127;
        float4 v = *(const float4*)&Whh[(size_t)(rank * COLS_CTA + r) * HID + k4 * 4];
        *(float4*)&sW[r * WSTR + k4 * 4] = v;
    }

    const uint32_t sh_local = smem_u32(sH);
    uint32_t peer[CLUSTER_N];
    #pragma unroll
    for (int r = 0; r < CLUSTER_N; ++r)
        peer[r] = (r == rank) ? sh_local : mapa32(sh_local, r);

    __syncthreads();

    // xp for this thread's 2x2 tile (only ks==0 lanes produce outputs)
    float2 xpA = make_float2(0.f, 0.f), xpB = xpA;
    if (ks == 0) {
        xpA = *(const float2*)&g_xp[(size_t)bG * HID + cG];
        xpB = *(const float2*)&g_xp[(size_t)(bG + 1) * HID + cG];
    }

    const ulonglong2* w2A = (const ulonglong2*)&sW[c0 * WSTR];
    const ulonglong2* w2B = (const ulonglong2*)&sW[(c0 + 1) * WSTR];
    const int ks32 = ks * 32;

    for (int t = 0; t < T_STEPS; ++t) {
        const int pc = t & 1;
        float s00 = 0.f, s01 = 0.f, s10 = 0.f, s11 = 0.f;  // (b, c): s<b><c>
        if (t > 0) {
            const int hb = (pc ^ 1) * (BPG * HROW);
            const ulonglong2* hA = (const ulonglong2*)&sH[hb + b0l * HROW + ks * 132];
            const ulonglong2* hB = (const ulonglong2*)&sH[hb + (b0l + 1) * HROW + ks * 132];
            unsigned long long a00 = 0ull, a01 = 0ull, a10 = 0ull, a11 = 0ull;
            #pragma unroll 8
            for (int i = 0; i < 32; ++i) {
                ulonglong2 wa = w2A[ks32 + i];
                ulonglong2 wb = w2B[ks32 + i];
                ulonglong2 ha = hA[i];
                ulonglong2 hbv = hB[i];
                FMA2(a00, ha.x,  wa.x); FMA2(a00, ha.y,  wa.y);
                FMA2(a01, ha.x,  wb.x); FMA2(a01, ha.y,  wb.y);
                FMA2(a10, hbv.x, wa.x); FMA2(a10, hbv.y, wa.y);
                FMA2(a11, hbv.x, wb.x); FMA2(a11, hbv.y, wb.y);
            }
            float lo, hi;
            asm("mov.b64 {%0, %1}, %2;" : "=f"(lo), "=f"(hi) : "l"(a00)); s00 = lo + hi;
            asm("mov.b64 {%0, %1}, %2;" : "=f"(lo), "=f"(hi) : "l"(a01)); s01 = lo + hi;
            asm("mov.b64 {%0, %1}, %2;" : "=f"(lo), "=f"(hi) : "l"(a10)); s10 = lo + hi;
            asm("mov.b64 {%0, %1}, %2;" : "=f"(lo), "=f"(hi) : "l"(a11)); s11 = lo + hi;
        }
        // reduce over the 4 k-splits (lanes differing in bits 0,1)
        s00 += __shfl_xor_sync(0xffffffffu, s00, 1);
        s01 += __shfl_xor_sync(0xffffffffu, s01, 1);
        s10 += __shfl_xor_sync(0xffffffffu, s10, 1);
        s11 += __shfl_xor_sync(0xffffffffu, s11, 1);
        s00 += __shfl_xor_sync(0xffffffffu, s00, 2);
        s01 += __shfl_xor_sync(0xffffffffu, s01, 2);
        s10 += __shfl_xor_sync(0xffffffffu, s10, 2);
        s11 += __shfl_xor_sync(0xffffffffu, s11, 2);

        if (t == T_STEPS - 1) {
            if (ks == 0) {
                float h00 = tanh_fast(xpA.x + s00);
                float h01 = tanh_fast(xpA.y + s01);
                float h10 = tanh_fast(xpB.x + s10);
                float h11 = tanh_fast(xpB.y + s11);
                float* gr = &g_rnn[(size_t)t * BH];
                *(float2*)&gr[(size_t)bG * HID + cG]       = make_float2(h00, h01);
                *(float2*)&gr[(size_t)(bG + 1) * HID + cG] = make_float2(h10, h11);
                *(float2*)&h_out[(size_t)bG * HID + cG]       = make_float2(h00, h01);
                *(float2*)&h_out[(size_t)(bG + 1) * HID + cG] = make_float2(h10, h11);
            }
            break;
        }

        if (ks == 0) {
            float h00 = tanh_fast(xpA.x + s00);
            float h01 = tanh_fast(xpA.y + s01);
            float h10 = tanh_fast(xpB.x + s10);
            float h11 = tanh_fast(xpB.y + s11);
            sC[b0l * COLS_CTA + c0]           = h00;
            sC[b0l * COLS_CTA + c0 + 1]       = h01;
            sC[(b0l + 1) * COLS_CTA + c0]     = h10;
            sC[(b0l + 1) * COLS_CTA + c0 + 1] = h11;
            // prefetch next xp
            xpA = *(const float2*)&g_xp[(size_t)(t + 1) * BH + (size_t)bG * HID + cG];
            xpB = *(const float2*)&g_xp[(size_t)(t + 1) * BH + (size_t)(bG + 1) * HID + cG];
        }
        __syncthreads();   // sC complete

        // push chunk to all 8 CTAs' sH[pc] + fire-and-forget g_rnn store
        for (int u = tid; u < 512 + 64; u += 256) {
            int rem = u & 63;
            int row = rem >> 4;       // local batch 0..3
            int f4  = rem & 15;       // f4 within 64-col chunk
            float4 v = *(float4*)&sC[row * COLS_CTA + f4 * 4];
            if (u < 512) {
                int r = u >> 6;       // target rank
                int m = rank * 16 + f4;   // global f4 index 0..127
                uint32_t off = (uint32_t)((pc * (BPG * HROW) + row * HROW + H_OFF(m)) * 4);
                uint32_t a = peer[r] + off;
                if (r == rank) st_shared_v4(a, v);
                else           st_cluster_v4(a, v);
            } else {
                *(float4*)&g_rnn[(size_t)t * BH + (size_t)(g * BPG + row) * HID
                                 + rank * COLS_CTA + f4 * 4] = v;
            }
        }

        cluster_sync_();   // release my DSMEM writes / acquire peers'; also block-syncs
    }
}

__global__ void dummy_k() {}

// -------------------- launch --------------------
extern "C" void kernel_launch(void* const* d_in, const int* in_sizes, int n_in,
                              void* d_out, int out_size)
{
    const float* x     = (const float*)d_in[0];
    const float* W_ih  = (const float*)d_in[1];
    const float* W_hh  = (const float*)d_in[2];
    const float* b_ih  = (const float*)d_in[3];
    const float* b_hh  = (const float*)d_in[4];
    const float* W_out = (const float*)d_in[5];
    const float* b_out = (const float*)d_in[6];

    float* y = (float*)d_out;                             // [T,B,O]
    float* h = y + (size_t)T_STEPS * BATCH * OUT_DIM;     // [1,B,H]

    float* xp  = nullptr;
    float* rnn = nullptr;
    cudaGetSymbolAddress((void**)&xp,  g_xp);
    cudaGetSymbolAddress((void**)&rnn, g_rnn);

    // K1: xp = x @ W_ih^T + b_ih + b_hh    (M=32768, N=512, K=256)
    {
        dim3 grid(HID / 64, M_ROWS / 128);
        sgemm_bt_bias<128, 64, 16, 8, 4, 256><<<grid, 256>>>(
            x, W_ih, b_ih, b_hh, xp, M_ROWS, HID, IN_DIM);
    }

    // two dummies so the scan sits at global launch #6 for ncu (-s 5 -c 1)
    dummy_k<<<1, 32>>>();
    dummy_k<<<1, 32>>>();

    // K2: clustered recurrence (128 CTAs); writes g_rnn + h_last
    cudaFuncSetAttribute(rnn_scan7, cudaFuncAttributeMaxDynamicSharedMemorySize,
                         SMEM_SCAN_BYTES);
    rnn_scan7<<<NCLUSTERS * CLUSTER_N, 256, SMEM_SCAN_BYTES>>>(W_hh, h);

    // K3: y = rnn_out @ W_out^T + b_out    (M=32768, N=256, K=512)
    {
        dim3 grid(OUT_DIM / 64, M_ROWS / 128);
        sgemm_bt_bias<128, 64, 16, 8, 4, 256><<<grid, 256>>>(
            rnn, W_out, b_out, nullptr, y, M_ROWS, OUT_DIM, HID);
    }
}

// round 11
// speedup vs baseline: 1.2228x; 1.2228x over previous
#include <cuda_runtime.h>
#include <math.h>
#include <stdint.h>

#define T_STEPS 512
#define BATCH   64
#define IN_DIM  256
#define HID     512
#define OUT_DIM 256
#define BH      (BATCH * HID)        // 32768
#define M_ROWS  (T_STEPS * BATCH)    // 32768

// Scratch (allocation-free rule: __device__ globals)
__device__ float g_xp[(size_t)M_ROWS * HID];   // xp = x@W_ih^T + b_ih + b_hh

// fast tanh: rel err ~1e-6, clamped (no NaN)
__device__ __forceinline__ float tanh_fast(float x) {
    float xc = fminf(9.0f, fmaxf(-9.0f, x));
    float e  = exp2f(2.885390081777927f * xc);   // e^(2x)
    return __fdividef(e - 1.0f, e + 1.0f);
}

// -------------------- SGEMM: C[M,N] = A[M,K] @ Bw[N,K]^T + bias --------------------
template<int BM, int BN, int BK, int TM, int TN, int THREADS>
__global__ __launch_bounds__(THREADS)
void sgemm_bt_bias(const float* __restrict__ A,
                   const float* __restrict__ Bw,
                   const float* __restrict__ bias0,
                   const float* __restrict__ bias1,
                   float* __restrict__ C,
                   int M, int N, int K)
{
    __shared__ float As[BK][BM];
    __shared__ float Bs[BK][BN];

    const int tid = threadIdx.x;
    const int tx  = tid % (BN / TN);
    const int ty  = tid / (BN / TN);
    const int m0  = blockIdx.y * BM;
    const int n0  = blockIdx.x * BN;

    float acc[TM][TN];
    #pragma unroll
    for (int i = 0; i < TM; ++i)
        #pragma unroll
        for (int j = 0; j < TN; ++j) acc[i][j] = 0.f;

    for (int k0 = 0; k0 < K; k0 += BK) {
        #pragma unroll
        for (int i = tid; i < (BM * BK) / 4; i += THREADS) {
            int r  = i / (BK / 4);
            int c4 = i % (BK / 4);
            float4 v = *(const float4*)&A[(size_t)(m0 + r) * K + k0 + c4 * 4];
            As[c4 * 4 + 0][r] = v.x;
            As[c4 * 4 + 1][r] = v.y;
            As[c4 * 4 + 2][r] = v.z;
            As[c4 * 4 + 3][r] = v.w;
        }
        #pragma unroll
        for (int i = tid; i < (BN * BK) / 4; i += THREADS) {
            int r  = i / (BK / 4);
            int c4 = i % (BK / 4);
            float4 v = *(const float4*)&Bw[(size_t)(n0 + r) * K + k0 + c4 * 4];
            Bs[c4 * 4 + 0][r] = v.x;
            Bs[c4 * 4 + 1][r] = v.y;
            Bs[c4 * 4 + 2][r] = v.z;
            Bs[c4 * 4 + 3][r] = v.w;
        }
        __syncthreads();

        #pragma unroll
        for (int kk = 0; kk < BK; ++kk) {
            float aR[TM], bR[TN];
            #pragma unroll
            for (int i = 0; i < TM; ++i) aR[i] = As[kk][ty * TM + i];
            #pragma unroll
            for (int j = 0; j < TN; ++j) bR[j] = Bs[kk][tx * TN + j];
            #pragma unroll
            for (int i = 0; i < TM; ++i)
                #pragma unroll
                for (int j = 0; j < TN; ++j)
                    acc[i][j] += aR[i] * bR[j];
        }
        __syncthreads();
    }

    float bj[TN];
    #pragma unroll
    for (int j = 0; j < TN; ++j) {
        int n = n0 + tx * TN + j;
        bj[j] = bias0[n] + (bias1 ? bias1[n] : 0.f);
    }
    #pragma unroll
    for (int i = 0; i < TM; ++i) {
        int m = m0 + ty * TM + i;
        #pragma unroll
        for (int j = 0; j < TN; ++j) {
            int n = n0 + tx * TN + j;
            C[(size_t)m * N + n] = acc[i][j] + bj[j];
        }
    }
}

// -------------------- fused scan + output GEMM (v8) --------------------
// 128 CTAs = 16 clusters (4 batches each) x 8 CTAs (64 h-cols / 32 out-cols each).
// 384 threads: tid<256 = h-warps (recurrence), tid>=256 = y-warps (y[t-1] GEMM,
// overlapped with h-compute; reads the stable ping-pong buffer).
// No h history in gmem; K3 eliminated.
#define CLUSTER_N 8
#define NCLUSTERS 16
#define COLS_CTA  64
#define BPG       4
#define OC_CTA    32                       // out-cols per CTA
#define WSTR      516
#define HSTR      520
#define SW_F   (COLS_CTA * WSTR)           // 33024
#define SWO_F  (OC_CTA * WSTR)             // 16512
#define SH_F   (2 * BPG * HSTR)            // 4160 (ping-pong)
#define SC_F   (BPG * COLS_CTA)            // 256
#define SMEM_SCAN_BYTES ((SW_F + SWO_F + SH_F + SC_F) * 4)   // 215808

__device__ __forceinline__ uint32_t smem_u32(const void* p) {
    uint32_t a;
    asm("{ .reg .u64 t; cvta.to.shared.u64 t, %1; cvt.u32.u64 %0, t; }"
        : "=r"(a) : "l"(p));
    return a;
}
__device__ __forceinline__ uint32_t mapa32(uint32_t addr, int rank) {
    uint32_t r;
    asm("mapa.shared::cluster.u32 %0, %1, %2;" : "=r"(r) : "r"(addr), "r"(rank));
    return r;
}
__device__ __forceinline__ void st_cluster_v4(uint32_t addr, float4 v) {
    asm volatile("st.shared::cluster.v4.f32 [%0], {%1,%2,%3,%4};"
                 :: "r"(addr), "f"(v.x), "f"(v.y), "f"(v.z), "f"(v.w) : "memory");
}
__device__ __forceinline__ void st_shared_v4(uint32_t addr, float4 v) {
    asm volatile("st.shared.v4.f32 [%0], {%1,%2,%3,%4};"
                 :: "r"(addr), "f"(v.x), "f"(v.y), "f"(v.z), "f"(v.w) : "memory");
}
__device__ __forceinline__ void cluster_sync_() {
    asm volatile("barrier.cluster.arrive.aligned;" ::: "memory");
    asm volatile("barrier.cluster.wait.aligned;" ::: "memory");
}
#define FMA2(acc, a, b) asm("fma.rn.f32x2 %0, %1, %2, %0;" : "+l"(acc) : "l"(a), "l"(b))

__global__ __launch_bounds__(384, 1) __cluster_dims__(CLUSTER_N, 1, 1)
void rnn_fused(const float* __restrict__ Whh,    // [HID, HID]
               const float* __restrict__ Wout,   // [OUT_DIM, HID]
               const float* __restrict__ b_out,  // [OUT_DIM]
               float* __restrict__ y,            // [T, B, O] (d_out)
               float* __restrict__ h_out)        // [B, HID]  (d_out tail)
{
    extern __shared__ float sm[];
    float* sW  = sm;                     // [64][WSTR]   W_hh slice
    float* sWo = sW + SW_F;              // [32][WSTR]   W_out slice
    float* sH  = sWo + SWO_F;            // [2][BPG][HSTR]
    float* sC  = sH + SH_F;              // [BPG][64]

    const int tid  = threadIdx.x;
    const int g    = blockIdx.x >> 3;    // batch group 0..15
    const int rank = blockIdx.x & 7;     // col group within cluster

    // h-thread mapping (tid < 256): warp covers 8 cols x 4 batches
    const int w = tid >> 5, l = tid & 31;
    const int c    = (w & 7) * 8 + (l & 7);    // 0..63 (valid for tid<256)
    const int bl   = l >> 3;                   // 0..3
    const int colg = rank * COLS_CTA + c;
    const int b    = g * BPG + bl;

    // y-thread mapping (tid >= 256): j = tid-256; 4 batches x 32 out-cols
    const int j   = tid - 256;
    const int yb  = (j >> 5) & 3;
    const int yoc = j & 31;
    const int ocg = rank * OC_CTA + yoc;

    // load W_hh rows [rank*64, +64) and W_out rows [rank*32, +32)
    for (int i = tid; i < COLS_CTA * (HID / 4); i += 384) {
        int r  = i >> 7;
        int k4 = i & 127;
        float4 v = *(const float4*)&Whh[(size_t)(rank * COLS_CTA + r) * HID + k4 * 4];
        *(float4*)&sW[r * WSTR + k4 * 4] = v;
    }
    for (int i = tid; i < OC_CTA * (HID / 4); i += 384) {
        int r  = i >> 7;
        int k4 = i & 127;
        float4 v = *(const float4*)&Wout[(size_t)(rank * OC_CTA + r) * HID + k4 * 4];
        *(float4*)&sWo[r * WSTR + k4 * 4] = v;
    }

    const uint32_t sh_local = smem_u32(sH);
    uint32_t peer[CLUSTER_N];
    #pragma unroll
    for (int r = 0; r < CLUSTER_N; ++r)
        peer[r] = (r == rank) ? sh_local : mapa32(sh_local, r);

    __syncthreads();

    float my_xp = 0.f, bo = 0.f;
    if (tid < 256) my_xp = g_xp[(size_t)b * HID + colg];   // t = 0
    else           bo    = b_out[ocg];

    const ulonglong2* w2  = (const ulonglong2*)&sW[c * WSTR];      // h-threads
    const ulonglong2* wo2 = (const ulonglong2*)&sWo[yoc * WSTR];   // y-threads

    for (int t = 0; t < T_STEPS; ++t) {
        const int pc = t & 1;            // buffer produced this step
        if (tid < 256) {
            // ---- recurrence: h[t] ----
            float acc = my_xp;
            if (t > 0) {
                const ulonglong2* h2 =
                    (const ulonglong2*)&sH[(pc ^ 1) * (BPG * HSTR) + bl * HSTR];
                unsigned long long a01 = 0ull, a23 = 0ull;
                #pragma unroll 8
                for (int k4 = 0; k4 < HID / 4; ++k4) {
                    ulonglong2 hv = h2[k4];
                    ulonglong2 wv = w2[k4];
                    FMA2(a01, hv.x, wv.x);
                    FMA2(a23, hv.y, wv.y);
                }
                float s0, s1, s2, s3;
                asm("mov.b64 {%0, %1}, %2;" : "=f"(s0), "=f"(s1) : "l"(a01));
                asm("mov.b64 {%0, %1}, %2;" : "=f"(s2), "=f"(s3) : "l"(a23));
                acc += (s0 + s1) + (s2 + s3);
            }
            float hn = tanh_fast(acc);
            sC[bl * COLS_CTA + c] = hn;
            if (t + 1 < T_STEPS)
                my_xp = g_xp[(size_t)(t + 1) * BH + (size_t)b * HID + colg];
            else
                h_out[(size_t)b * HID + colg] = hn;
        } else if (t > 0) {
            // ---- fused output GEMM: y[t-1] from stable buffer sH[pc^1] ----
            const ulonglong2* hy =
                (const ulonglong2*)&sH[(pc ^ 1) * (BPG * HSTR) + yb * HSTR];
            unsigned long long a01 = 0ull, a23 = 0ull;
            #pragma unroll 8
            for (int k4 = 0; k4 < HID / 4; ++k4) {
                ulonglong2 hv = hy[k4];
                ulonglong2 wv = wo2[k4];
                FMA2(a01, hv.x, wv.x);
                FMA2(a23, hv.y, wv.y);
            }
            float s0, s1, s2, s3;
            asm("mov.b64 {%0, %1}, %2;" : "=f"(s0), "=f"(s1) : "l"(a01));
            asm("mov.b64 {%0, %1}, %2;" : "=f"(s2), "=f"(s3) : "l"(a23));
            y[(size_t)(t - 1) * (BATCH * OUT_DIM) + (size_t)(g * BPG + yb) * OUT_DIM + ocg]
                = bo + (s0 + s1) + (s2 + s3);
        }

        __syncthreads();   // sC complete; y-warps done with sH[pc^1]

        // push chunk to all 8 CTAs' sH[pc] (8 ranks x 4 rows x 16 f4 = 512 units)
        for (int u = tid; u < 512; u += 384) {
            int rem = u & 63;
            int row = rem >> 4;
            int f4  = rem & 15;
            float4 v = *(float4*)&sC[row * COLS_CTA + f4 * 4];
            int r = u >> 6;
            uint32_t a = peer[r] +
                (uint32_t)(((pc * BPG + row) * HSTR + rank * 64 + f4 * 4) * 4);
            if (r == rank) st_shared_v4(a, v);
            else           st_cluster_v4(a, v);
        }

        cluster_sync_();
    }

    // epilogue: y[511] from sH[1] (h[T-1], fully exchanged)
    if (tid >= 256) {
        const ulonglong2* hy = (const ulonglong2*)&sH[1 * (BPG * HSTR) + yb * HSTR];
        unsigned long long a01 = 0ull, a23 = 0ull;
        #pragma unroll 8
        for (int k4 = 0; k4 < HID / 4; ++k4) {
            ulonglong2 hv = hy[k4];
            ulonglong2 wv = wo2[k4];
            FMA2(a01, hv.x, wv.x);
            FMA2(a23, hv.y, wv.y);
        }
        float s0, s1, s2, s3;
        asm("mov.b64 {%0, %1}, %2;" : "=f"(s0), "=f"(s1) : "l"(a01));
        asm("mov.b64 {%0, %1}, %2;" : "=f"(s2), "=f"(s3) : "l"(a23));
        y[(size_t)(T_STEPS - 1) * (BATCH * OUT_DIM) + (size_t)(g * BPG + yb) * OUT_DIM + ocg]
            = bo + (s0 + s1) + (s2 + s3);
    }
}

// -------------------- launch --------------------
extern "C" void kernel_launch(void* const* d_in, const int* in_sizes, int n_in,
                              void* d_out, int out_size)
{
    const float* x     = (const float*)d_in[0];
    const float* W_ih  = (const float*)d_in[1];
    const float* W_hh  = (const float*)d_in[2];
    const float* b_ih  = (const float*)d_in[3];
    const float* b_hh  = (const float*)d_in[4];
    const float* W_out = (const float*)d_in[5];
    const float* b_out = (const float*)d_in[6];

    float* y = (float*)d_out;                             // [T,B,O]
    float* h = y + (size_t)T_STEPS * BATCH * OUT_DIM;     // [1,B,H]

    float* xp = nullptr;
    cudaGetSymbolAddress((void**)&xp, g_xp);

    // K1: xp = x @ W_ih^T + b_ih + b_hh    (M=32768, N=512, K=256)
    {
        dim3 grid(HID / 64, M_ROWS / 128);
        sgemm_bt_bias<128, 64, 16, 8, 4, 256><<<grid, 256>>>(
            x, W_ih, b_ih, b_hh, xp, M_ROWS, HID, IN_DIM);
    }

    // K2: fused recurrence + output GEMM (2 launches/call -> global L6 = call2's
    // fused kernel, profiled by ncu -s 5 -c 1)
    cudaFuncSetAttribute(rnn_fused, cudaFuncAttributeMaxDynamicSharedMemorySize,
                         SMEM_SCAN_BYTES);
    rnn_fused<<<NCLUSTERS * CLUSTER_N, 384, SMEM_SCAN_BYTES>>>(
        W_hh, W_out, b_out, y, h);
}

// round 12
// speedup vs baseline: 1.8711x; 1.5302x over previous
#include <cuda_runtime.h>
#include <math.h>
#include <stdint.h>

#define T_STEPS 512
#define BATCH   64
#define IN_DIM  256
#define HID     512
#define OUT_DIM 256
#define BH      (BATCH * HID)        // 32768
#define M_ROWS  (T_STEPS * BATCH)    // 32768

// Scratch (allocation-free rule: __device__ globals)
__device__ float g_xp[(size_t)M_ROWS * HID];   // xp = x@W_ih^T + b_ih + b_hh
__device__ float g_rnn[(size_t)M_ROWS * HID];  // h history (exchange medium)

// ---- barrier state: monotonic flags + persistent epoch ----
#define SCAN_CTAS 128
#define NGROUPS   4     // batch groups
#define CGS       32    // col groups per batch group
__device__ __align__(128) unsigned g_flags2[NGROUPS][32];  // one 128B line per group
__device__ unsigned g_epoch;

__device__ __forceinline__ unsigned ld_acq(const unsigned* p) {
    unsigned v;
    asm volatile("ld.acquire.gpu.u32 %0, [%1];" : "=r"(v) : "l"(p));
    return v;
}
__device__ __forceinline__ void st_rel(unsigned* p, unsigned v) {
    asm volatile("st.release.gpu.u32 [%0], %1;" :: "l"(p), "r"(v));
}

// fast tanh: rel err ~1e-6, clamped (no NaN)
__device__ __forceinline__ float tanh_fast(float x) {
    float xc = fminf(9.0f, fmaxf(-9.0f, x));
    float e  = exp2f(2.885390081777927f * xc);   // e^(2x)
    return __fdividef(e - 1.0f, e + 1.0f);
}

#define FMA2(acc, a, b) asm("fma.rn.f32x2 %0, %1, %2, %0;" : "+l"(acc) : "l"(a), "l"(b))

// -------------------- SGEMM: C[M,N] = A[M,K] @ Bw[N,K]^T + bias --------------------
template<int BM, int BN, int BK, int TM, int TN, int THREADS>
__global__ __launch_bounds__(THREADS)
void sgemm_bt_bias(const float* __restrict__ A,
                   const float* __restrict__ Bw,
                   const float* __restrict__ bias0,
                   const float* __restrict__ bias1,
                   float* __restrict__ C,
                   int M, int N, int K)
{
    __shared__ float As[BK][BM];
    __shared__ float Bs[BK][BN];

    const int tid = threadIdx.x;
    const int tx  = tid % (BN / TN);
    const int ty  = tid / (BN / TN);
    const int m0  = blockIdx.y * BM;
    const int n0  = blockIdx.x * BN;

    float acc[TM][TN];
    #pragma unroll
    for (int i = 0; i < TM; ++i)
        #pragma unroll
        for (int j = 0; j < TN; ++j) acc[i][j] = 0.f;

    for (int k0 = 0; k0 < K; k0 += BK) {
        #pragma unroll
        for (int i = tid; i < (BM * BK) / 4; i += THREADS) {
            int r  = i / (BK / 4);
            int c4 = i % (BK / 4);
            float4 v = *(const float4*)&A[(size_t)(m0 + r) * K + k0 + c4 * 4];
            As[c4 * 4 + 0][r] = v.x;
            As[c4 * 4 + 1][r] = v.y;
            As[c4 * 4 + 2][r] = v.z;
            As[c4 * 4 + 3][r] = v.w;
        }
        #pragma unroll
        for (int i = tid; i < (BN * BK) / 4; i += THREADS) {
            int r  = i / (BK / 4);
            int c4 = i % (BK / 4);
            float4 v = *(const float4*)&Bw[(size_t)(n0 + r) * K + k0 + c4 * 4];
            Bs[c4 * 4 + 0][r] = v.x;
            Bs[c4 * 4 + 1][r] = v.y;
            Bs[c4 * 4 + 2][r] = v.z;
            Bs[c4 * 4 + 3][r] = v.w;
        }
        __syncthreads();

        #pragma unroll
        for (int kk = 0; kk < BK; ++kk) {
            float aR[TM], bR[TN];
            #pragma unroll
            for (int i = 0; i < TM; ++i) aR[i] = As[kk][ty * TM + i];
            #pragma unroll
            for (int j = 0; j < TN; ++j) bR[j] = Bs[kk][tx * TN + j];
            #pragma unroll
            for (int i = 0; i < TM; ++i)
                #pragma unroll
                for (int j = 0; j < TN; ++j)
                    acc[i][j] += aR[i] * bR[j];
        }
        __syncthreads();
    }

    float bj[TN];
    #pragma unroll
    for (int j = 0; j < TN; ++j) {
        int n = n0 + tx * TN + j;
        bj[j] = bias0[n] + (bias1 ? bias1[n] : 0.f);
    }
    #pragma unroll
    for (int i = 0; i < TM; ++i) {
        int m = m0 + ty * TM + i;
        #pragma unroll
        for (int j = 0; j < TN; ++j) {
            int n = n0 + tx * TN + j;
            C[(size_t)m * N + n] = acc[i][j] + bj[j];
        }
    }
}

// -------------------- fused scan + y GEMM (v9, R3 skeleton) --------------------
// 128 CTAs = 32 col-groups x 4 batch-groups. CTA: 16 h-cols x 16 batches,
// plus 8 y-cols x 16 batches of the output GEMM computed INSIDE the barrier
// window (between flag release and flag poll) from the stable sH = h[t-1].
#define COLS_PER_CTA 16
#define BPC          16
#define OC_CTA       8            // y-cols per col-group (256/32)
#define WS           516
#define HS           520
#define SW_F   (COLS_PER_CTA * WS)   // 8256 floats
#define SWO_F  (OC_CTA * WS)         // 4128
#define SH_F   (BPC * HS)            // 8320
#define SY_F   256
#define SMEM_SCAN_BYTES ((SW_F + SWO_F + SH_F + SY_F) * 4)   // 83840

__global__ __launch_bounds__(256)
void rnn_scan9(const float* __restrict__ Whh,    // [HID, HID]
               const float* __restrict__ Wout,   // [OUT_DIM, HID]
               const float* __restrict__ b_out,  // [OUT_DIM]
               float* __restrict__ y,            // [T, B, O] (d_out)
               float* __restrict__ h_out)        // [B, HID]  (d_out tail)
{
    extern __shared__ float sm[];
    float* sW  = sm;                // [16][WS]  W_hh rows (h-cols of this cg)
    float* sWo = sW + SW_F;         // [8][WS]   W_out rows (y-cols of this cg)
    float* sH  = sWo + SWO_F;       // [16][HS]  h[t-1] for this bh group
    float* sY  = sH + SH_F;         // [256] y partials (kh=1 halves)
    __shared__ unsigned s_base;

    const int tid = threadIdx.x;
    const int bid = blockIdx.x;
    const int bh  = bid & 3;
    const int cg  = bid >> 2;

    // h mapping: warp covers 8 cols x 4 batches (R4 shape)
    const int w = tid >> 5, l = tid & 31;
    const int c  = ((w & 1) << 3) + (l & 7);     // 0..15
    const int bl = ((w >> 1) << 2) + (l >> 3);   // 0..15
    const int colg = cg * COLS_PER_CTA + c;
    const int b    = bh * BPC + bl;
    const int b0   = bh * BPC;

    // y mapping: o = tid&127 -> (yb = o>>3 in 0..15, oc = o&7), kh = tid>>7
    const int o   = tid & 127;
    const int yb  = o >> 3;
    const int oc  = o & 7;
    const int kh  = tid >> 7;
    const int ocg = cg * OC_CTA + oc;
    const float bo = b_out[ocg];

    if (tid == 0) s_base = *(volatile unsigned*)&g_epoch;

    // cache W_hh rows [cg*16, +16) and W_out rows [cg*8, +8)
    for (int i = tid; i < COLS_PER_CTA * (HID / 4); i += 256) {
        int r  = i >> 7;
        int k4 = i & 127;
        float4 v = *(const float4*)&Whh[(size_t)(cg * COLS_PER_CTA + r) * HID + k4 * 4];
        *(float4*)&sW[r * WS + k4 * 4] = v;
    }
    for (int i = tid; i < OC_CTA * (HID / 4); i += 256) {
        int r  = i >> 7;
        int k4 = i & 127;
        float4 v = *(const float4*)&Wout[(size_t)(cg * OC_CTA + r) * HID + k4 * 4];
        *(float4*)&sWo[r * WS + k4 * 4] = v;
    }
    __syncthreads();
    const unsigned base = s_base;

    float my_xp = g_xp[(size_t)b * HID + colg];   // t = 0

    const ulonglong2* h2r = (const ulonglong2*)&sH[bl * HS];          // h compute
    const ulonglong2* w2  = (const ulonglong2*)&sW[c * WS];
    const ulonglong2* hy2 = (const ulonglong2*)&sH[yb * HS] + kh * 64; // y compute
    const ulonglong2* wo2 = (const ulonglong2*)&sWo[oc * WS] + kh * 64;

    for (int t = 0; t < T_STEPS; ++t) {
        // ---- h[t] = tanh(xp + h[t-1] @ Whh_slice^T) ----
        float acc = my_xp;
        if (t > 0) {
            unsigned long long a01 = 0ull, a23 = 0ull;
            #pragma unroll 8
            for (int k4 = 0; k4 < HID / 4; ++k4) {
                ulonglong2 hv = h2r[k4];
                ulonglong2 wv = w2[k4];
                FMA2(a01, hv.x, wv.x);
                FMA2(a23, hv.y, wv.y);
            }
            float s0, s1, s2, s3;
            asm("mov.b64 {%0, %1}, %2;" : "=f"(s0), "=f"(s1) : "l"(a01));
            asm("mov.b64 {%0, %1}, %2;" : "=f"(s2), "=f"(s3) : "l"(a23));
            acc += (s0 + s1) + (s2 + s3);
        }
        float hn = tanh_fast(acc);
        g_rnn[(size_t)t * BH + (size_t)b * HID + colg] = hn;
        if (t == T_STEPS - 1)
            h_out[(size_t)b * HID + colg] = hn;

        __syncthreads();                      // all h[t] stores of this CTA issued
        if (tid == 0)
            st_rel(&g_flags2[bh][cg], base + (unsigned)t + 1u);  // publish

        // ---- gap work: y[t-1] partial from STABLE sH (= h[t-1]) ----
        float part = 0.f;
        if (t > 0) {
            unsigned long long a01 = 0ull, a23 = 0ull;
            #pragma unroll 8
            for (int k4 = 0; k4 < 64; ++k4) {     // half of HID/4
                ulonglong2 hv = hy2[k4];
                ulonglong2 wv = wo2[k4];
                FMA2(a01, hv.x, wv.x);
                FMA2(a23, hv.y, wv.y);
            }
            float s0, s1, s2, s3;
            asm("mov.b64 {%0, %1}, %2;" : "=f"(s0), "=f"(s1) : "l"(a01));
            asm("mov.b64 {%0, %1}, %2;" : "=f"(s2), "=f"(s3) : "l"(a23));
            part = (s0 + s1) + (s2 + s3);
            if (kh) sY[o] = part;
        }

        // ---- barrier: wait for whole bh group to publish h[t] ----
        const unsigned target = base + (unsigned)t + 1u;
        if (tid < 32) {
            bool ok;
            do {
                unsigned v = ld_acq(&g_flags2[bh][tid]);
                ok = __all_sync(0xffffffffu, (int)(v - target) >= 0);
            } while (!ok);
        }
        __syncthreads();                      // flags seen; sY visible

        if (t > 0 && !kh)
            y[(size_t)(t - 1) * (BATCH * OUT_DIM) + (size_t)(b0 + yb) * OUT_DIM + ocg]
                = bo + part + sY[o];

        // ---- stage h[t] rows b0..b0+15 into sH; prefetch next xp ----
        const float* src = &g_rnn[(size_t)t * BH + (size_t)b0 * HID];
        #pragma unroll
        for (int i = tid; i < BPC * (HID / 4); i += 256) {
            int r  = i >> 7;
            int k4 = i & 127;
            float4 v = *(const float4*)&src[(size_t)r * HID + k4 * 4];
            *(float4*)&sH[r * HS + k4 * 4] = v;
        }
        if (t + 1 < T_STEPS)
            my_xp = g_xp[(size_t)(t + 1) * BH + (size_t)b * HID + colg];
        __syncthreads();                      // sH = h[t] complete
    }

    // ---- epilogue: y[511] from sH = h[511] ----
    {
        unsigned long long a01 = 0ull, a23 = 0ull;
        #pragma unroll 8
        for (int k4 = 0; k4 < 64; ++k4) {
            ulonglong2 hv = hy2[k4];
            ulonglong2 wv = wo2[k4];
            FMA2(a01, hv.x, wv.x);
            FMA2(a23, hv.y, wv.y);
        }
        float s0, s1, s2, s3;
        asm("mov.b64 {%0, %1}, %2;" : "=f"(s0), "=f"(s1) : "l"(a01));
        asm("mov.b64 {%0, %1}, %2;" : "=f"(s2), "=f"(s3) : "l"(a23));
        float part = (s0 + s1) + (s2 + s3);
        if (kh) sY[o] = part;
        __syncthreads();
        if (!kh)
            y[(size_t)(T_STEPS - 1) * (BATCH * OUT_DIM) + (size_t)(b0 + yb) * OUT_DIM + ocg]
                = bo + part + sY[o];
    }

    // advance epoch for the next launch (monotonic flags)
    if (bid == 0 && tid == 0)
        *(volatile unsigned*)&g_epoch = base + (unsigned)T_STEPS;
}

__global__ void dummy_k() {}

// -------------------- launch --------------------
extern "C" void kernel_launch(void* const* d_in, const int* in_sizes, int n_in,
                              void* d_out, int out_size)
{
    const float* x     = (const float*)d_in[0];
    const float* W_ih  = (const float*)d_in[1];
    const float* W_hh  = (const float*)d_in[2];
    const float* b_ih  = (const float*)d_in[3];
    const float* b_hh  = (const float*)d_in[4];
    const float* W_out = (const float*)d_in[5];
    const float* b_out = (const float*)d_in[6];

    float* y = (float*)d_out;                             // [T,B,O]
    float* h = y + (size_t)T_STEPS * BATCH * OUT_DIM;     // [1,B,H]

    float* xp = nullptr;
    cudaGetSymbolAddress((void**)&xp, g_xp);

    // K1: xp = x @ W_ih^T + b_ih + b_hh    (M=32768, N=512, K=256)
    {
        dim3 grid(HID / 64, M_ROWS / 128);
        sgemm_bt_bias<128, 64, 16, 8, 4, 256><<<grid, 256>>>(
            x, W_ih, b_ih, b_hh, xp, M_ROWS, HID, IN_DIM);
    }

    // two dummies so the fused scan sits at global launch #6 for ncu (-s 5 -c 1)
    dummy_k<<<1, 32>>>();
    dummy_k<<<1, 32>>>();

    // K2: fused recurrence + output GEMM; writes y + h_last
    cudaFuncSetAttribute(rnn_scan9, cudaFuncAttributeMaxDynamicSharedMemorySize,
                         SMEM_SCAN_BYTES);
    rnn_scan9<<<SCAN_CTAS, 256, SMEM_SCAN_BYTES>>>(W_hh, W_out, b_out, y, h);
}